// round 1
// baseline (speedup 1.0000x reference)
#include <cuda_runtime.h>
#include <cstdint>

// ShapeRetrieval: fused cosine-sim + argmax retrieval.
// Inputs (metadata order): query_embedding f32[2048,256], gallery_embedding f32[100000,256],
//                          shape_idx_table i32[100000]
// Output (f32[3*2048]): [idx | max_sim | retrieved]

#define N_Q 2048
#define M_G 100000
#define D_K 256

#define BQ 128          // query rows per block tile
#define BG 128          // gallery cols per block tile
#define KT 8            // k-slice per smem stage
#define TS 132          // smem row stride (128 + 4): 16B-aligned rows, conflict-free
#define CHUNK 512       // gallery cols per block (4 tiles of 128)
#define NTILES (CHUNK / BG)
#define NCHUNK ((M_G + CHUNK - 1) / CHUNK)   // 196

__device__ float g_qn[N_Q * D_K];            // normalized queries
__device__ float g_inv[M_G];                  // gallery 1/norm
__device__ unsigned long long g_best[N_Q];    // packed (orderable_key << 32) | ~idx

// ---------------------------------------------------------------------------
// Kernel 1: normalize queries (one block per row) + reset g_best
// ---------------------------------------------------------------------------
__global__ void qnorm_kernel(const float* __restrict__ q) {
    int row = blockIdx.x;
    int tid = threadIdx.x;
    float v = q[row * D_K + tid];
    float s = v * v;
    #pragma unroll
    for (int m = 16; m > 0; m >>= 1) s += __shfl_xor_sync(0xffffffffu, s, m);
    __shared__ float ws[8];
    if ((tid & 31) == 0) ws[tid >> 5] = s;
    __syncthreads();
    if (tid < 8) {
        float t = ws[tid];
        #pragma unroll
        for (int m = 4; m > 0; m >>= 1) t += __shfl_xor_sync(0xffu, t, m);
        if (tid == 0) ws[0] = t;
    }
    __syncthreads();
    float scale = 1.0f / fmaxf(sqrtf(ws[0]), 1e-12f);
    g_qn[row * D_K + tid] = v * scale;
    if (tid == 0) g_best[row] = 0ull;   // any real key > 0
}

// ---------------------------------------------------------------------------
// Kernel 2: gallery inverse norms (one warp per row)
// ---------------------------------------------------------------------------
__global__ void gnorm_kernel(const float* __restrict__ g) {
    int warp = (blockIdx.x * blockDim.x + threadIdx.x) >> 5;
    if (warp >= M_G) return;
    int lane = threadIdx.x & 31;
    const float4* p = (const float4*)(g + (size_t)warp * D_K);
    float4 a = p[lane];
    float4 b = p[lane + 32];
    float s = a.x*a.x + a.y*a.y + a.z*a.z + a.w*a.w
            + b.x*b.x + b.y*b.y + b.z*b.z + b.w*b.w;
    #pragma unroll
    for (int m = 16; m > 0; m >>= 1) s += __shfl_xor_sync(0xffffffffu, s, m);
    if (lane == 0) g_inv[warp] = 1.0f / fmaxf(sqrtf(s), 1e-12f);
}

// ---------------------------------------------------------------------------
// Kernel 3: main SGEMM + fused running argmax.
// Grid: (NCHUNK, N_Q/BQ). Block: 256 threads, 8x8 microtile -> 128x128 tile.
// ---------------------------------------------------------------------------
__global__ __launch_bounds__(256, 2)
void sim_kernel(const float* __restrict__ gal) {
    __shared__ __align__(16) float Qs[KT * TS];
    __shared__ __align__(16) float Gs[KT * TS];

    int tid = threadIdx.x;
    int tx = tid & 15;
    int ty = tid >> 4;
    int qbase  = blockIdx.y * BQ;
    int cbase0 = blockIdx.x * CHUNK;

    // per-thread loader coords: one float4 of Q-tile and one of G-tile per stage
    int lrow = tid >> 1;            // 0..127
    int lk4  = (tid & 1) << 2;      // 0 or 4

    float bestv[8];
    unsigned int besti[8];
    #pragma unroll
    for (int i = 0; i < 8; i++) { bestv[i] = -3.4e38f; besti[i] = 0u; }

    int mleft = M_G - cbase0;
    int ntile = (mleft < CHUNK) ? ((mleft + BG - 1) / BG) : NTILES;

    for (int t = 0; t < ntile; t++) {
        int cbase = cbase0 + t * BG;

        float acc[8][8];
        #pragma unroll
        for (int i = 0; i < 8; i++)
            #pragma unroll
            for (int j = 0; j < 8; j++) acc[i][j] = 0.0f;

        // prefetch stage 0
        const float* qptr = &g_qn[(qbase + lrow) * D_K + lk4];
        int gcol = cbase + lrow;
        const float* gptr = gal + (size_t)gcol * D_K + lk4;
        float4 qv = *(const float4*)qptr;
        float4 gv = make_float4(0.f, 0.f, 0.f, 0.f);
        if (gcol < M_G) gv = *(const float4*)gptr;

        #pragma unroll 4
        for (int kk = 0; kk < D_K; kk += KT) {
            __syncthreads();
            Qs[(lk4+0)*TS + lrow] = qv.x; Qs[(lk4+1)*TS + lrow] = qv.y;
            Qs[(lk4+2)*TS + lrow] = qv.z; Qs[(lk4+3)*TS + lrow] = qv.w;
            Gs[(lk4+0)*TS + lrow] = gv.x; Gs[(lk4+1)*TS + lrow] = gv.y;
            Gs[(lk4+2)*TS + lrow] = gv.z; Gs[(lk4+3)*TS + lrow] = gv.w;
            __syncthreads();

            // prefetch next stage while computing this one
            if (kk + KT < D_K) {
                qv = *(const float4*)(qptr + kk + KT);
                if (gcol < M_G) gv = *(const float4*)(gptr + kk + KT);
            }

            #pragma unroll
            for (int k = 0; k < KT; k++) {
                float4 qa = *(const float4*)&Qs[k*TS + (ty << 2)];
                float4 qb = *(const float4*)&Qs[k*TS + 64 + (ty << 2)];
                float4 ga = *(const float4*)&Gs[k*TS + (tx << 2)];
                float4 gb = *(const float4*)&Gs[k*TS + 64 + (tx << 2)];
                float qr[8] = {qa.x,qa.y,qa.z,qa.w, qb.x,qb.y,qb.z,qb.w};
                float gr[8] = {ga.x,ga.y,ga.z,ga.w, gb.x,gb.y,gb.z,gb.w};
                #pragma unroll
                for (int i = 0; i < 8; i++)
                    #pragma unroll
                    for (int j = 0; j < 8; j++)
                        acc[i][j] = fmaf(qr[i], gr[j], acc[i][j]);
            }
        }

        // epilogue: scale by gallery inv-norm, fold into running argmax
        #pragma unroll
        for (int j = 0; j < 8; j++) {
            int col = cbase + ((j < 4) ? ((tx << 2) + j) : (64 + (tx << 2) + (j - 4)));
            if (col < M_G) {
                float inv = g_inv[col];
                #pragma unroll
                for (int i = 0; i < 8; i++) {
                    float v = acc[i][j] * inv;
                    if (v > bestv[i]) { bestv[i] = v; besti[i] = (unsigned int)col; }
                }
            }
        }
    }

    // reduce over the 16 tx lanes (columns), then one atomicMax per query row
    #pragma unroll
    for (int i = 0; i < 8; i++) {
        float v = bestv[i];
        unsigned int ci = besti[i];
        #pragma unroll
        for (int m = 1; m < 16; m <<= 1) {
            float ov = __shfl_xor_sync(0xffffffffu, v, m);
            unsigned int oc = __shfl_xor_sync(0xffffffffu, ci, m);
            if (ov > v || (ov == v && oc < ci)) { v = ov; ci = oc; }
        }
        if (tx == 0) {
            int qrow = qbase + ((i < 4) ? ((ty << 2) + i) : (64 + (ty << 2) + (i - 4)));
            unsigned int u = __float_as_uint(v);
            unsigned int key = (u & 0x80000000u) ? ~u : (u | 0x80000000u);
            unsigned long long packed =
                ((unsigned long long)key << 32) | (unsigned long long)(~ci);
            atomicMax(&g_best[qrow], packed);
        }
    }
}

// ---------------------------------------------------------------------------
// Kernel 4: unpack winners, write outputs [idx | max_sim | retrieved] as f32
// ---------------------------------------------------------------------------
__global__ void out_kernel(const int* __restrict__ table, float* __restrict__ out) {
    int n = blockIdx.x * blockDim.x + threadIdx.x;
    if (n >= N_Q) return;
    unsigned long long p = g_best[n];
    unsigned int ci  = ~(unsigned int)p;
    unsigned int key = (unsigned int)(p >> 32);
    unsigned int u   = (key & 0x80000000u) ? (key & 0x7FFFFFFFu) : ~key;
    out[n]           = (float)ci;
    out[N_Q + n]     = __uint_as_float(u);
    out[2 * N_Q + n] = (float)table[ci];
}

// ---------------------------------------------------------------------------
extern "C" void kernel_launch(void* const* d_in, const int* in_sizes, int n_in,
                              void* d_out, int out_size) {
    const float* q     = (const float*)d_in[0];
    const float* g     = (const float*)d_in[1];
    const int*   table = (const int*)d_in[2];
    float* out = (float*)d_out;

    qnorm_kernel<<<N_Q, 256>>>(q);
    gnorm_kernel<<<(M_G * 32 + 255) / 256, 256>>>(g);
    dim3 grid(NCHUNK, N_Q / BQ);
    sim_kernel<<<grid, 256>>>(g);
    out_kernel<<<(N_Q + 255) / 256, 256>>>(table, out);
}

// round 3
// speedup vs baseline: 1.8434x; 1.8434x over previous
#include <cuda_runtime.h>
#include <cuda_bf16.h>
#include <cstdint>

// ShapeRetrieval: cosine-sim argmax via bf16 hi/lo mma.sync GEMM + fp64 rescore.
// (sm_100 base target: no tcgen05 — legacy HMMA path.)
// Inputs: query f32[2048,256], gallery f32[100000,256], table i32[100000]
// Output f32[3*2048]: [idx | max_sim | retrieved]

#define N_Q     2048
#define M_G     100000
#define M_PAD   100096          // 782 * 128
#define D_K     256
#define NTILE   782
#define GROUPS  9
#define QBLOCKS 16
#define TPG     87

#define SM_QH      0            // 128 x 256 bf16 = 64KB
#define SM_QL      65536        // 64KB
#define SM_RING    131072       // 8 stages x 8KB
#define STAGE_B    8192
#define NSTAGE     8
#define SMEM_TOTAL (131072 + NSTAGE * STAGE_B)   // 196608

__device__ __nv_bfloat16 g_qhi[N_Q * D_K];
__device__ __nv_bfloat16 g_qlo[N_Q * D_K];
__device__ __nv_bfloat16 g_ghi[(size_t)M_PAD * D_K];
__device__ __nv_bfloat16 g_glo[(size_t)M_PAD * D_K];
__device__ unsigned int  g_cand_idx[N_Q * GROUPS * 2];

// ------------------------------------------------------------------ helpers
__device__ __forceinline__ uint32_t smem_u32(const void* p) {
    uint32_t a;
    asm("{ .reg .u64 t; cvta.to.shared.u64 t, %1; cvt.u32.u64 %0, t; }"
        : "=r"(a) : "l"(p));
    return a;
}
__device__ __forceinline__ void cpa16(uint32_t dst, const void* src) {
    asm volatile("cp.async.cg.shared.global [%0], [%1], 16;"
                 :: "r"(dst), "l"(src) : "memory");
}
__device__ __forceinline__ void cp_commit() {
    asm volatile("cp.async.commit_group;" ::: "memory");
}
template<int N> __device__ __forceinline__ void cp_wait() {
    asm volatile("cp.async.wait_group %0;" :: "n"(N) : "memory");
}
__device__ __forceinline__ void ldmx4(uint32_t& r0, uint32_t& r1,
                                      uint32_t& r2, uint32_t& r3, uint32_t a) {
    asm volatile("ldmatrix.sync.aligned.m8n8.x4.shared.b16 {%0,%1,%2,%3}, [%4];"
                 : "=r"(r0), "=r"(r1), "=r"(r2), "=r"(r3) : "r"(a));
}
__device__ __forceinline__ void mma16816(float* c, const uint32_t* a,
                                         uint32_t b0, uint32_t b1) {
    asm volatile(
        "mma.sync.aligned.m16n8k16.row.col.f32.bf16.bf16.f32 "
        "{%0,%1,%2,%3}, {%4,%5,%6,%7}, {%8,%9}, {%0,%1,%2,%3};"
        : "+f"(c[0]), "+f"(c[1]), "+f"(c[2]), "+f"(c[3])
        : "r"(a[0]), "r"(a[1]), "r"(a[2]), "r"(a[3]), "r"(b0), "r"(b1));
}
__device__ __forceinline__ bool better(float av, unsigned ai, float bv, unsigned bi) {
    return (av > bv) || (av == bv && ai < bi);
}

// ------------------------------------------------------------------ prep
__global__ void qprep_kernel(const float* __restrict__ q) {
    int row = blockIdx.x, tid = threadIdx.x;
    float v = q[row * D_K + tid];
    float s = v * v;
    #pragma unroll
    for (int m = 16; m > 0; m >>= 1) s += __shfl_xor_sync(0xffffffffu, s, m);
    __shared__ float ws[8];
    if ((tid & 31) == 0) ws[tid >> 5] = s;
    __syncthreads();
    if (tid < 8) {
        float t = ws[tid];
        #pragma unroll
        for (int m = 4; m > 0; m >>= 1) t += __shfl_xor_sync(0xffu, t, m);
        if (tid == 0) ws[0] = t;
    }
    __syncthreads();
    float y = v * (1.0f / fmaxf(sqrtf(ws[0]), 1e-12f));
    __nv_bfloat16 h = __float2bfloat16(y);
    g_qhi[row * D_K + tid] = h;
    g_qlo[row * D_K + tid] = __float2bfloat16(y - __bfloat162float(h));
}

__global__ void gprep_kernel(const float* __restrict__ g) {
    int warp = (blockIdx.x * blockDim.x + threadIdx.x) >> 5;
    if (warp >= M_PAD) return;
    int lane = threadIdx.x & 31;
    size_t base = (size_t)warp * D_K;
    if (warp < M_G) {
        const float4* p = (const float4*)(g + base);
        float4 a = p[lane], b = p[lane + 32];
        float s = a.x*a.x + a.y*a.y + a.z*a.z + a.w*a.w
                + b.x*b.x + b.y*b.y + b.z*b.z + b.w*b.w;
        #pragma unroll
        for (int m = 16; m > 0; m >>= 1) s += __shfl_xor_sync(0xffffffffu, s, m);
        float inv = 1.0f / fmaxf(sqrtf(s), 1e-12f);
        float va[8] = {a.x*inv, a.y*inv, a.z*inv, a.w*inv,
                       b.x*inv, b.y*inv, b.z*inv, b.w*inv};
        #pragma unroll
        for (int k = 0; k < 8; k++) {
            size_t off = base + ((k < 4) ? (lane*4 + k) : (128 + lane*4 + k - 4));
            __nv_bfloat16 h = __float2bfloat16(va[k]);
            g_ghi[off] = h;
            g_glo[off] = __float2bfloat16(va[k] - __bfloat162float(h));
        }
    } else {
        #pragma unroll
        for (int k = 0; k < 8; k++) {
            size_t off = base + ((k < 4) ? (lane*4 + k) : (128 + lane*4 + k - 4));
            g_ghi[off] = __float2bfloat16(0.0f);
            g_glo[off] = __float2bfloat16(0.0f);
        }
    }
}

// ------------------------------------------------------------------ main GEMM
// grid (QBLOCKS, GROUPS), 256 threads: 8 warps = 4m x 2n, warp tile 32x64.
__global__ __launch_bounds__(256, 1)
void sim_kernel() {
    extern __shared__ __align__(1024) char smem[];
    const uint32_t sb = smem_u32(smem);
    const int tid  = threadIdx.x;
    const int lane = tid & 31, wid = tid >> 5;
    const int wm = wid & 3, wn = wid >> 2;
    const int qbase = blockIdx.x * 128;
    const int t0 = blockIdx.y * TPG;
    const int ntl = (t0 + TPG <= NTILE) ? TPG : (NTILE - t0);
    const int NS = ntl * 16;

    // ---- resident Q load (hi+lo), swizzled rows
    for (int i = tid; i < 8192; i += 256) {
        int arr = i >> 12, rc = i & 4095;
        int row = rc >> 5, c = rc & 31;
        const __nv_bfloat16* src = (arr ? g_qlo : g_qhi)
                                 + (size_t)(qbase + row) * D_K + c * 8;
        cpa16(sb + (arr ? SM_QL : SM_QH) + row * 512 + ((c ^ (row & 7)) << 4), src);
    }
    cp_commit();

    // ---- slice issue: slice j = tile (j>>4), s=j&15; s<8: ghi kc=s; s>=8: glo kc=s-8
    auto issue = [&](int j) {
        int tile = j >> 4, s = j & 15;
        const __nv_bfloat16* gsrc = (s < 8) ? g_ghi : g_glo;
        size_t base = (size_t)(t0 + tile) * 128 * D_K + (size_t)(s & 7) * 32;
        uint32_t stg = sb + SM_RING + (j & 7) * STAGE_B;
        #pragma unroll
        for (int h = 0; h < 2; h++) {
            int idx = tid + h * 256;
            int r = idx >> 2, c = idx & 3;
            cpa16(stg + r * 64 + (((c ^ ((r >> 1) & 3))) << 4),
                  gsrc + base + (size_t)r * D_K + c * 8);
        }
        cp_commit();
    };
    for (int j = 0; j < 7; j++) issue(j);

    // ---- per-thread constant address pieces
    const int arow0 = wm * 32 + (lane & 7) + ((lane >> 3) & 1) * 8;
    const int aswz  = arow0 & 7;
    const uint32_t aoffH = sb + SM_QH + arow0 * 512;
    const uint32_t aoffL = sb + SM_QL + arow0 * 512;
    const int achk = lane >> 4;
    const int bn0  = ((lane >> 4) << 3) + (lane & 7);
    const int bswz = (bn0 >> 1) & 3;
    const int bchk = (lane >> 3) & 1;
    const uint32_t boff = wn * 64 * 64 + bn0 * 64;   // within stage

    float acc[2][8][4];
    #pragma unroll
    for (int mt = 0; mt < 2; mt++)
        #pragma unroll
        for (int nt = 0; nt < 8; nt++)
            #pragma unroll
            for (int e = 0; e < 4; e++) acc[mt][nt][e] = 0.0f;

    float v1[4], v2[4]; unsigned c1[4], c2[4];
    #pragma unroll
    for (int s = 0; s < 4; s++) { v1[s] = v2[s] = -3.4e38f; c1[s] = c2[s] = 0u; }

    #pragma unroll 1
    for (int j = 0; j < NS; j++) {
        cp_wait<6>();
        __syncthreads();
        if (j + 7 < NS) issue(j + 7);
        const int s = j & 15;
        const uint32_t stg = sb + SM_RING + (j & 7) * STAGE_B;
        const int cq = (s & 7) * 4;

        #pragma unroll
        for (int ks = 0; ks < 2; ks++) {
            uint32_t b[16];
            #pragma unroll
            for (int p = 0; p < 4; p++)
                ldmx4(b[4*p], b[4*p+1], b[4*p+2], b[4*p+3],
                      stg + boff + p * 1024 + ((((ks << 1) + bchk) ^ bswz) << 4));
            uint32_t ah[2][4];
            #pragma unroll
            for (int mt = 0; mt < 2; mt++)
                ldmx4(ah[mt][0], ah[mt][1], ah[mt][2], ah[mt][3],
                      aoffH + mt * 8192 + (((cq + (ks << 1) + achk) ^ aswz) << 4));
            #pragma unroll
            for (int mt = 0; mt < 2; mt++)
                #pragma unroll
                for (int nt = 0; nt < 8; nt++)
                    mma16816(acc[mt][nt], ah[mt], b[nt*2], b[nt*2+1]);
            if (s < 8) {   // ghi slice: also accumulate qlo * ghi
                uint32_t al[2][4];
                #pragma unroll
                for (int mt = 0; mt < 2; mt++)
                    ldmx4(al[mt][0], al[mt][1], al[mt][2], al[mt][3],
                          aoffL + mt * 8192 + (((cq + (ks << 1) + achk) ^ aswz) << 4));
                #pragma unroll
                for (int mt = 0; mt < 2; mt++)
                    #pragma unroll
                    for (int nt = 0; nt < 8; nt++)
                        mma16816(acc[mt][nt], al[mt], b[nt*2], b[nt*2+1]);
            }
        }

        if (s == 15) {   // tile done: fold into running top-2, reset acc
            const int colbase = (t0 + (j >> 4)) * 128 + wn * 64 + (lane & 3) * 2;
            #pragma unroll
            for (int mt = 0; mt < 2; mt++) {
                #pragma unroll
                for (int nt = 0; nt < 8; nt++) {
                    unsigned c0 = colbase + nt * 8;
                    #pragma unroll
                    for (int e = 0; e < 4; e++) {
                        float v = acc[mt][nt][e];
                        unsigned col = c0 + (e & 1);
                        int sl = mt * 2 + (e >> 1);
                        if (col < M_G) {
                            if (v > v1[sl]) { v2[sl]=v1[sl]; c2[sl]=c1[sl];
                                              v1[sl]=v;      c1[sl]=col; }
                            else if (v > v2[sl]) { v2[sl]=v; c2[sl]=col; }
                        }
                        acc[mt][nt][e] = 0.0f;
                    }
                }
            }
        }
    }

    // ---- merge across the 4 lanes of each quad (same rows)
    #pragma unroll
    for (int m = 1; m <= 2; m <<= 1) {
        #pragma unroll
        for (int s = 0; s < 4; s++) {
            float ov1 = __shfl_xor_sync(0xffffffffu, v1[s], m);
            float ov2 = __shfl_xor_sync(0xffffffffu, v2[s], m);
            unsigned oc1 = __shfl_xor_sync(0xffffffffu, c1[s], m);
            unsigned oc2 = __shfl_xor_sync(0xffffffffu, c2[s], m);
            if (better(ov1, oc1, v1[s], c1[s])) {
                if (better(v1[s], c1[s], ov2, oc2)) { v2[s]=v1[s]; c2[s]=c1[s]; }
                else                                { v2[s]=ov2;   c2[s]=oc2; }
                v1[s] = ov1; c1[s] = oc1;
            } else if (better(ov1, oc1, v2[s], c2[s])) {
                v2[s] = ov1; c2[s] = oc1;
            }
        }
    }

    __syncthreads();                         // ring no longer needed: reuse as epi buf
    float* epi = (float*)(smem + SM_RING);   // [2 wn][128 rows][4]
    if ((lane & 3) == 0) {
        #pragma unroll
        for (int s = 0; s < 4; s++) {
            int row = wm * 32 + (s >> 1) * 16 + (lane >> 2) + (s & 1) * 8;
            float* e = epi + ((wn * 128 + row) << 2);
            e[0] = v1[s]; e[1] = __uint_as_float(c1[s]);
            e[2] = v2[s]; e[3] = __uint_as_float(c2[s]);
        }
    }
    __syncthreads();
    if (tid < 128) {
        const float* ea = epi + (tid << 2);
        const float* eb = epi + ((128 + tid) << 2);
        float av1 = ea[0], av2 = ea[2], bv1 = eb[0], bv2 = eb[2];
        unsigned ai1 = __float_as_uint(ea[1]), ai2 = __float_as_uint(ea[3]);
        unsigned bi1 = __float_as_uint(eb[1]), bi2 = __float_as_uint(eb[3]);
        float f1, f2; unsigned j1, j2;
        if (better(av1, ai1, bv1, bi1)) {
            f1 = av1; j1 = ai1;
            if (better(bv1, bi1, av2, ai2)) { f2 = bv1; j2 = bi1; }
            else                            { f2 = av2; j2 = ai2; }
        } else {
            f1 = bv1; j1 = bi1;
            if (better(av1, ai1, bv2, bi2)) { f2 = av1; j2 = ai1; }
            else                            { f2 = bv2; j2 = bi2; }
        }
        (void)f1; (void)f2;
        size_t o = ((size_t)(qbase + tid) * GROUPS + blockIdx.y) * 2;
        g_cand_idx[o]     = j1;
        g_cand_idx[o + 1] = j2;
    }
}

// ------------------------------------------------------------------ rescore
__global__ void rescore_kernel(const float* __restrict__ q,
                               const float* __restrict__ g,
                               const int* __restrict__ table,
                               float* __restrict__ out) {
    int qi = blockIdx.x;
    int lane = threadIdx.x & 31, w = threadIdx.x >> 5;
    __shared__ double s_sim[24];
    __shared__ unsigned s_idx[24];
    const float* qp = q + (size_t)qi * D_K;
    float qv[8]; double qn = 0.0;
    #pragma unroll
    for (int k = 0; k < 8; k++) { qv[k] = qp[k*32 + lane]; qn += (double)qv[k]*qv[k]; }
    #pragma unroll
    for (int m = 16; m > 0; m >>= 1) qn += __shfl_xor_sync(0xffffffffu, qn, m);

    for (int c = w; c < 2 * GROUPS; c += 4) {
        unsigned col = g_cand_idx[(size_t)qi * GROUPS * 2 + c];
        const float* gp = g + (size_t)col * D_K;
        double dot = 0.0, gn = 0.0;
        #pragma unroll
        for (int k = 0; k < 8; k++) {
            double gvv = gp[k*32 + lane];
            dot += (double)qv[k] * gvv;
            gn  += gvv * gvv;
        }
        #pragma unroll
        for (int m = 16; m > 0; m >>= 1) {
            dot += __shfl_xor_sync(0xffffffffu, dot, m);
            gn  += __shfl_xor_sync(0xffffffffu, gn, m);
        }
        if (lane == 0) {
            s_sim[c] = dot / (fmax(sqrt(qn), 1e-12) * fmax(sqrt(gn), 1e-12));
            s_idx[c] = col;
        }
    }
    __syncthreads();
    if (threadIdx.x == 0) {
        double best = -1e300; unsigned bi = 0xffffffffu;
        for (int c = 0; c < 2 * GROUPS; c++) {
            if (s_sim[c] > best || (s_sim[c] == best && s_idx[c] < bi)) {
                best = s_sim[c]; bi = s_idx[c];
            }
        }
        out[qi]         = (float)bi;
        out[N_Q + qi]   = (float)best;
        out[2*N_Q + qi] = (float)table[bi];
    }
}

// ----------------------------------------------------------------------------
extern "C" void kernel_launch(void* const* d_in, const int* in_sizes, int n_in,
                              void* d_out, int out_size) {
    const float* q     = (const float*)d_in[0];
    const float* g     = (const float*)d_in[1];
    const int*   table = (const int*)d_in[2];
    float* out = (float*)d_out;

    cudaFuncSetAttribute(sim_kernel,
        cudaFuncAttributeMaxDynamicSharedMemorySize, SMEM_TOTAL);

    qprep_kernel<<<N_Q, 256>>>(q);
    gprep_kernel<<<M_PAD / 8, 256>>>(g);
    sim_kernel<<<dim3(QBLOCKS, GROUPS), 256, SMEM_TOTAL>>>();
    rescore_kernel<<<N_Q, 128>>>(q, g, table, out);
}